// round 8
// baseline (speedup 1.0000x reference)
#include <cuda_runtime.h>
#include <cstdint>

// LBP semantic dependency, difference-space. 6-CTA cluster per (i,b) problem:
// rank r -> (type t = r>>1, parity c = r&1). Each CTA holds d[t] restricted to
// cells (j,k) with (j+k)&1==c (transpose partner same class -> CTA-local),
// plus P = 2^(p*log2e) staged in smem ONCE (iteration-invariant).
// Eval is mask-free: rowsum = unconditional sum of D; diagonal and zero-weight
// columns are subtracted in the per-row DB phase (cost ~nothing).

#define S    160
#define S2   25600
#define S3   4096000
#define HS   80
#define DP   81          /* d pitch (odd: conflict-free row writes) */
#define PP   80          /* ps pitch */
#define NTH  512
#define LOG2E 1.4426950408889634f

/* shared layout (floats) */
#define OFF_D    0                    /* d[160][81] = 12960 */
#define OFF_PS   12960                /* P[160][80] = 12800 */
#define OFF_DB   25760                /* deltab[160] */
#define OFF_SE   25920
#define OFF_W    26080
#define OFF_MJ   26240
#define OFF_RS   26400                /* local rowsum[160] */
#define OFF_ACC  26560                /* peer partial sums [2][160] */
#define OFF_ZL   26880                /* zero-w column list (ints) [160] */
#define OFF_ZN   27040                /* count */
#define SMEM_FLOATS (OFF_ZN + 1)
#define SMEM_BYTES  (SMEM_FLOATS * 4)

extern __shared__ float sm[];

__device__ __forceinline__ uint32_t smem_u32(const void* p) {
    uint32_t a;
    asm("{ .reg .u64 t; cvta.to.shared.u64 t, %1; cvt.u32.u64 %0, t; }"
        : "=r"(a) : "l"(p));
    return a;
}
__device__ __forceinline__ void cluster_sync_() {
    asm volatile("barrier.cluster.arrive.aligned;" ::: "memory");
    asm volatile("barrier.cluster.wait.aligned;" ::: "memory");
}
__device__ __forceinline__ void red_remote_add_f32(uint32_t laddr, uint32_t rank, float v) {
    asm volatile(
        "{ .reg .b32 r; mapa.shared::cluster.u32 r, %0, %1; "
        "red.relaxed.cluster.shared::cluster.add.f32 [r], %2; }"
        :: "r"(laddr), "r"(rank), "f"(v) : "memory");
}
__device__ __forceinline__ float ex2f_(float x) {
    float y; asm("ex2.approx.ftz.f32 %0, %1;" : "=f"(y) : "f"(x)); return y;
}
__device__ __forceinline__ float lg2f_(float x) {
    float y; asm("lg2.approx.ftz.f32 %0, %1;" : "=f"(y) : "f"(x)); return y;
}
__device__ __forceinline__ bool mask_at(const void* m, bool byteMask, int idx) {
    if (byteMask) return ((const unsigned char*)m)[idx] != 0;
    return ((const uint32_t*)m)[idx] != 0u;
}

__global__ void __launch_bounds__(NTH, 2) __cluster_dims__(6, 1, 1)
lbp_kernel(const float* __restrict__ s_edge,
           const float* __restrict__ s_sib,
           const float* __restrict__ s_cop,
           const float* __restrict__ s_grd,
           const void* __restrict__ mask,
           float* __restrict__ out)
{
    const int tid  = threadIdx.x;
    const int bx   = blockIdx.x;
    const int rank = bx % 6;
    const int prob = bx / 6;
    const int i    = prob % S;
    const int b    = prob / S;
    const int t    = rank >> 1;      /* score type */
    const int c    = rank & 1;       /* pair-parity class */

    const bool byteMask = (*(const uint32_t*)mask == 0x01010101u);

    float* __restrict__ D  = sm + OFF_D;
    float* __restrict__ PS = sm + OFF_PS;
    float* __restrict__ DB = sm + OFF_DB;
    int*   __restrict__ ZL = (int*)(sm + OFF_ZL);

    const float* __restrict__ P =
        (t == 0 ? s_sib : (t == 1 ? s_cop : s_grd)) + (size_t)b * S3 + i * S;

    /* ---- init: zero d, stage P = 2^(p*log2e) (only needed cols), scalars */
    #pragma unroll 4
    for (int u = 0; u < 26; ++u) {
        const int x = tid + NTH * u;
        if (x < S * DP) D[x] = 0.f;
    }
    #pragma unroll 5
    for (int u = 0; u < 25; ++u) {
        const int e   = tid + NTH * u;          /* 12800 = 512*25 exactly */
        const int ch  = e % PP;
        const int r   = e / PP;
        const int col = 2 * ch + ((r + c) & 1);
        PS[r * PP + ch] = ex2f_(P[(size_t)r * S2 + col] * LOG2E);
    }
    if (tid < S) {
        const int k = tid;
        const bool mk = mask_at(mask, byteMask, b * S2 + k * S + i);
        sm[OFF_W  + k] = (mk && (k != i)) ? 1.f : 0.f;
        sm[OFF_MJ + k] = mk ? 1.f : 0.f;
        sm[OFF_SE + k] = s_edge[b * S2 + k * S + i] * LOG2E;
        DB[k] = 0.f;
        sm[OFF_RS + k] = 0.f;
        sm[OFF_ACC + k] = 0.f;
        sm[OFF_ACC + S + k] = 0.f;
    }
    __syncthreads();
    /* deterministic zero-weight column list (usually just {i}) */
    if (tid == 0) {
        int zn = 0;
        for (int k = 0; k < S; ++k)
            if (sm[OFF_W + k] == 0.f) ZL[zn++] = k;
        ((int*)(sm + OFF_ZN))[0] = zn;
    }
    __syncthreads();
    cluster_sync_();   /* all ranks' ACC zeroed before any remote red */

    const uint32_t accAddr = smem_u32(sm + OFF_ACC);
    const int zn = ((int*)(sm + OFF_ZN))[0];
    float dbFinal = 0.f;

    for (int it = 0; it < 3; ++it) {
        /* ---- stage transpose partners d_old[k][j] into regs ----
           cell (jv, k), k = kB + 32*a; partner d[k][jv] at row k, col jv>>1 */
        float dreg[25];
        #pragma unroll
        for (int v = 0; v < 5; ++v) {
            const int jm  = tid + NTH * v;
            const int kkB = jm / S;
            const int jv  = jm - kkB * S;
            const int kB  = 2 * kkB + (c ^ (jv & 1));
            const int tb  = kB * DP + (jv >> 1);
            #pragma unroll
            for (int a = 0; a < 5; ++a)
                dreg[v * 5 + a] = D[tb + DP * 32 * a];
        }
        __syncthreads();   /* all reads of d before any writes */

        /* ---- compute new message differences (mask-free accumulate) ---- */
        float acc[5];
        #pragma unroll
        for (int v = 0; v < 5; ++v) {
            const int jm  = tid + NTH * v;
            const int kkB = jm / S;
            const int jv  = jm - kkB * S;
            const int par = c ^ (jv & 1);
            const int kB  = 2 * kkB + par;
            const int psb = kB * PP + (jv >> 1);
            const int wb  = jv * DP + kkB;
            float av = 0.f;
            #pragma unroll
            for (int a = 0; a < 5; ++a) {
                const int k  = kB + 32 * a;
                const float aa = fminf(fmaxf(DB[k] - dreg[v * 5 + a], -30.f), 30.f);
                const float e  = ex2f_(aa);
                const float Pv = PS[psb + PP * 32 * a];
                const float Dv = lg2f_(fmaf(e, Pv, 1.f)) - lg2f_(e + 1.f);
                D[wb + 16 * a] = Dv;
                av += Dv;
            }
            acc[v] = av;
        }
        #pragma unroll
        for (int v = 0; v < 5; ++v) {
            const int jm = tid + NTH * v;
            const int jv = jm - (jm / S) * S;
            atomicAdd(&sm[OFF_RS + jv], acc[v]);
        }
        __syncthreads();   /* d + RS complete */

        /* ---- per-row corrections + Δb all-reduce across the 6 ranks ---- */
        const int buf = it & 1;
        float myPart = 0.f;
        if (tid < S) {
            float corr = 0.f;
            if (c == 0) corr = D[tid * DP + (tid >> 1)];        /* diagonal */
            for (int z = 0; z < zn; ++z) {                      /* w[zk]==0 */
                const int zk = ZL[z];
                if (zk != tid && (((tid + zk) & 1) == c))
                    corr += D[tid * DP + (zk >> 1)];
            }
            myPart = sm[OFF_RS + tid] - corr;
            const uint32_t dst = accAddr + 4u * (uint32_t)(buf * S + tid);
            #pragma unroll
            for (int r = 0; r < 6; ++r)
                if (r != rank) red_remote_add_f32(dst, (uint32_t)r, myPart);
        }
        cluster_sync_();   /* peer partials landed */
        if (tid < S) {
            const float tot = myPart + sm[OFF_ACC + buf * S + tid];
            sm[OFF_ACC + buf * S + tid] = 0.f;      /* re-arm for it+2 */
            sm[OFF_RS + tid] = 0.f;
            dbFinal = sm[OFF_SE + tid] + sm[OFF_MJ + tid] * tot;
            DB[tid] = dbFinal;
        }
        /* next iter's post-stage __syncthreads orders DB/RS/ACC for all */
    }

    /* ---- output: out[b, j, i, :] = softmax over channels (base-2) ---- */
    if (rank == 0 && tid < S) {
        const float Dv = dbFinal;
        const float e  = ex2f_(-fabsf(Dv));
        const float pb = 1.f / (1.f + e);
        const float ps = e * pb;
        const float p1 = (Dv >= 0.f) ? pb : ps;
        const float p0 = (Dv >= 0.f) ? ps : pb;
        float* o = out + ((size_t)((b * S + tid) * S + i)) * 2;
        o[0] = p0;
        o[1] = p1;
    }
}

extern "C" void kernel_launch(void* const* d_in, const int* in_sizes, int n_in,
                              void* d_out, int out_size) {
    (void)in_sizes; (void)n_in; (void)out_size;
    cudaFuncSetAttribute(lbp_kernel,
                         cudaFuncAttributeMaxDynamicSharedMemorySize, SMEM_BYTES);
    const float* s_edge = (const float*)d_in[0];
    const float* s_sib  = (const float*)d_in[1];
    const float* s_cop  = (const float*)d_in[2];
    const float* s_grd  = (const float*)d_in[3];
    const void*  mask   = d_in[4];
    float* outp = (float*)d_out;

    lbp_kernel<<<2 * S * 6, NTH, SMEM_BYTES>>>(
        s_edge, s_sib, s_cop, s_grd, mask, outp);
}

// round 9
// speedup vs baseline: 1.2289x; 1.2289x over previous
#include <cuda_runtime.h>
#include <cstdint>

// LBP semantic dependency, difference-space, RATIO-SPACE state.
// 6-CTA cluster per (i,b): rank -> (type t=r>>1, parity c=r&1).
// State X[j][k] = 2^(-d[j][k]) for cells (j+k)&1==c (transpose partner local).
// Per cell: e = E[k]*Xold[k][j]; r = (1+e)*rcp(1+e*P); Xnew = r; d = -lg2(r).
// Only 2 MUFU per cell. P = 2^(p*log2e) staged once (iteration-invariant).
// Thread tile = 5 rows (jv = tr+32r, same parity) x 5 cols (k = 10*tc+2s+par)
// so E[k], W[k] are hoisted (5 LDS each per thread, not per cell).

#define S    160
#define S2   25600
#define S3   4096000
#define DP   81          /* X pitch */
#define PP   80          /* PS pitch */
#define NTH  512
#define LOG2E 1.4426950408889634f

/* shared layout (floats) */
#define OFF_X    0                    /* X[160][81] = 12960 */
#define OFF_PS   12960                /* P[160][80] = 12800 */
#define OFF_DB   25760
#define OFF_SE   25920
#define OFF_W    26080
#define OFF_MJ   26240
#define OFF_RS   26400
#define OFF_ACC  26560                /* [2][160] */
#define OFF_EX   26880                /* E[k] = 2^clamp(DB[k]) */
#define SMEM_FLOATS (OFF_EX + S)
#define SMEM_BYTES  (SMEM_FLOATS * 4)

extern __shared__ float sm[];

__device__ __forceinline__ uint32_t smem_u32(const void* p) {
    uint32_t a;
    asm("{ .reg .u64 t; cvta.to.shared.u64 t, %1; cvt.u32.u64 %0, t; }"
        : "=r"(a) : "l"(p));
    return a;
}
__device__ __forceinline__ void cluster_sync_() {
    asm volatile("barrier.cluster.arrive.aligned;" ::: "memory");
    asm volatile("barrier.cluster.wait.aligned;" ::: "memory");
}
__device__ __forceinline__ void red_remote_add_f32(uint32_t laddr, uint32_t rank, float v) {
    asm volatile(
        "{ .reg .b32 r; mapa.shared::cluster.u32 r, %0, %1; "
        "red.relaxed.cluster.shared::cluster.add.f32 [r], %2; }"
        :: "r"(laddr), "r"(rank), "f"(v) : "memory");
}
__device__ __forceinline__ float ex2f_(float x) {
    float y; asm("ex2.approx.ftz.f32 %0, %1;" : "=f"(y) : "f"(x)); return y;
}
__device__ __forceinline__ float lg2f_(float x) {
    float y; asm("lg2.approx.ftz.f32 %0, %1;" : "=f"(y) : "f"(x)); return y;
}
__device__ __forceinline__ float rcpf_(float x) {
    float y; asm("rcp.approx.ftz.f32 %0, %1;" : "=f"(y) : "f"(x)); return y;
}
__device__ __forceinline__ bool mask_at(const void* m, bool byteMask, int idx) {
    if (byteMask) return ((const unsigned char*)m)[idx] != 0;
    return ((const uint32_t*)m)[idx] != 0u;
}

__global__ void __launch_bounds__(NTH, 2) __cluster_dims__(6, 1, 1)
lbp_kernel(const float* __restrict__ s_edge,
           const float* __restrict__ s_sib,
           const float* __restrict__ s_cop,
           const float* __restrict__ s_grd,
           const void* __restrict__ mask,
           float* __restrict__ out)
{
    const int tid  = threadIdx.x;
    const int bx   = blockIdx.x;
    const int rank = bx % 6;
    const int prob = bx / 6;
    const int i    = prob % S;
    const int b    = prob / S;
    const int t    = rank >> 1;      /* score type */
    const int c    = rank & 1;       /* pair-parity class */

    const int tr    = tid & 31;              /* lane: row group */
    const int tc    = tid >> 5;              /* warp: col group */
    const int par   = c ^ (tr & 1);          /* fixed column parity */
    const int kbase = 10 * tc + par;         /* k_s = kbase + 2s */

    const bool byteMask = (*(const uint32_t*)mask == 0x01010101u);

    float* __restrict__ X  = sm + OFF_X;
    float* __restrict__ PS = sm + OFF_PS;
    float* __restrict__ DB = sm + OFF_DB;
    float* __restrict__ EX = sm + OFF_EX;

    const float* __restrict__ P =
        (t == 0 ? s_sib : (t == 1 ? s_cop : s_grd)) + (size_t)b * S3 + i * S;

    /* ---- init: X = 1 (d = 0), stage P = 2^(p*log2e), scalars ---- */
    #pragma unroll 4
    for (int u = 0; u < 26; ++u) {
        const int x = tid + NTH * u;
        if (x < S * DP) X[x] = 1.f;
    }
    #pragma unroll 5
    for (int u = 0; u < 25; ++u) {
        const int e   = tid + NTH * u;          /* 12800 = 512*25 */
        const int ch  = e % PP;
        const int r   = e / PP;
        const int col = 2 * ch + ((r + c) & 1);
        PS[r * PP + ch] = ex2f_(P[(size_t)r * S2 + col] * LOG2E);
    }
    if (tid < S) {
        const int k = tid;
        const bool mk = mask_at(mask, byteMask, b * S2 + k * S + i);
        sm[OFF_W  + k] = (mk && (k != i)) ? 1.f : 0.f;
        sm[OFF_MJ + k] = mk ? 1.f : 0.f;
        sm[OFF_SE + k] = s_edge[b * S2 + k * S + i] * LOG2E;
        DB[k] = 0.f;
        EX[k] = 1.f;
        sm[OFF_RS + k] = 0.f;
        sm[OFF_ACC + k] = 0.f;
        sm[OFF_ACC + S + k] = 0.f;
    }
    __syncthreads();
    cluster_sync_();   /* all ranks' ACC zeroed before any remote red */

    const uint32_t accAddr = smem_u32(sm + OFF_ACC);
    float dbFinal = 0.f;

    for (int it = 0; it < 3; ++it) {
        /* ---- stage transpose partners X_old[k][jv] into regs ----
           cell (jv=tr+32r, k=kbase+2s); partner at X[k][jv>>1] */
        float Xold[25];
        #pragma unroll
        for (int r = 0; r < 5; ++r) {
            const int rb = (tr >> 1) + 16 * r;
            #pragma unroll
            for (int s = 0; s < 5; ++s)
                Xold[r * 5 + s] = X[(kbase + 2 * s) * DP + rb];
        }
        __syncthreads();   /* all reads before any writes */

        /* ---- hoisted per-column scalars ---- */
        float Ereg[5], Wreg[5];
        #pragma unroll
        for (int s = 0; s < 5; ++s) {
            Ereg[s] = EX[kbase + 2 * s];
            Wreg[s] = sm[OFF_W + kbase + 2 * s];
        }

        /* ---- eval: 2 MUFU / cell ---- */
        float acc[5];
        #pragma unroll
        for (int r = 0; r < 5; ++r) {
            const int jv  = tr + 32 * r;
            const int psb = (tr >> 1) + 16 * r;
            const int wrow = jv * DP + 5 * tc;
            float av = 0.f;
            #pragma unroll
            for (int s = 0; s < 5; ++s) {
                const int k  = kbase + 2 * s;
                const float Pv  = PS[k * PP + psb];
                const float e   = Ereg[s] * Xold[r * 5 + s];
                const float num = fmaf(e, Pv, 1.f);
                const float den = e + 1.f;
                const float rr  = den * rcpf_(num);   /* 2^(-d_new) */
                X[wrow + s] = rr;
                const float dn  = lg2f_(rr);          /* = -d_new */
                const float wc  = (k == jv) ? 0.f : Wreg[s];
                av = fmaf(wc, dn, av);                /* av = -sum w*d */
            }
            acc[r] = av;
        }
        #pragma unroll
        for (int r = 0; r < 5; ++r)
            atomicAdd(&sm[OFF_RS + tr + 32 * r], acc[r]);
        __syncthreads();   /* X writes + RS complete */

        /* ---- Δb all-reduce across the 6 ranks (RS holds -rowsum) ---- */
        const int buf = it & 1;
        float myPart = 0.f;
        if (tid < S) {
            myPart = sm[OFF_RS + tid];
            const uint32_t dst = accAddr + 4u * (uint32_t)(buf * S + tid);
            #pragma unroll
            for (int r = 0; r < 6; ++r)
                if (r != rank) red_remote_add_f32(dst, (uint32_t)r, myPart);
        }
        cluster_sync_();   /* peer partials landed */
        if (tid < S) {
            const float tot = -(myPart + sm[OFF_ACC + buf * S + tid]);
            sm[OFF_ACC + buf * S + tid] = 0.f;      /* re-arm for it+2 */
            sm[OFF_RS + tid] = 0.f;
            dbFinal = sm[OFF_SE + tid] + sm[OFF_MJ + tid] * tot;
            DB[tid] = dbFinal;
            EX[tid] = ex2f_(fminf(fmaxf(dbFinal, -30.f), 30.f));
        }
        /* next iter's post-stage __syncthreads orders DB/EX/RS/ACC */
    }

    /* ---- output: out[b, j, i, :] = softmax over channels (base-2) ---- */
    if (rank == 0 && tid < S) {
        const float Dv = dbFinal;
        const float e  = ex2f_(-fabsf(Dv));
        const float pb = 1.f / (1.f + e);
        const float ps = e * pb;
        const float p1 = (Dv >= 0.f) ? pb : ps;
        const float p0 = (Dv >= 0.f) ? ps : pb;
        float* o = out + ((size_t)((b * S + tid) * S + i)) * 2;
        o[0] = p0;
        o[1] = p1;
    }
}

extern "C" void kernel_launch(void* const* d_in, const int* in_sizes, int n_in,
                              void* d_out, int out_size) {
    (void)in_sizes; (void)n_in; (void)out_size;
    cudaFuncSetAttribute(lbp_kernel,
                         cudaFuncAttributeMaxDynamicSharedMemorySize, SMEM_BYTES);
    const float* s_edge = (const float*)d_in[0];
    const float* s_sib  = (const float*)d_in[1];
    const float* s_cop  = (const float*)d_in[2];
    const float* s_grd  = (const float*)d_in[3];
    const void*  mask   = d_in[4];
    float* outp = (float*)d_out;

    lbp_kernel<<<2 * S * 6, NTH, SMEM_BYTES>>>(
        s_edge, s_sib, s_cop, s_grd, mask, outp);
}

// round 10
// speedup vs baseline: 1.4248x; 1.1594x over previous
#include <cuda_runtime.h>
#include <cstdint>

// LBP semantic dependency, difference-space, ratio-space state X = 2^(-d).
// 6-CTA cluster per (i,b): rank -> (type t=r>>1, parity c=r&1).
// PS evicted from smem: it=0 computes Pv=2^(p*log2e) from raw p (DRAM) and
// stores it to a global scratch (coalesced, per-CTA 51KB slice -> L2-hot);
// iters 1-2 re-load Pv via LDG. smem = 57KB/CTA -> 3 CTAs/SM (48 warps).

#define S    160
#define S2   25600
#define S3   4096000
#define DP   81          /* X pitch */
#define NTH  512
#define LOG2E 1.4426950408889634f

/* shared layout (floats) */
#define OFF_X    0                    /* X[160][81] = 12960 */
#define OFF_DB   12960
#define OFF_SE   13120
#define OFF_W    13280
#define OFF_MJ   13440
#define OFF_RS   13600
#define OFF_ACC  13760                /* [2][160] */
#define OFF_EX   14080
#define SMEM_FLOATS (OFF_EX + S)
#define SMEM_BYTES  (SMEM_FLOATS * 4)

/* global scratch for Pv: [b][i][rank][k(160)][jh(80)] = 98.3 MB */
__device__ float P2g[2 * 160 * 6 * 160 * 80];

extern __shared__ float sm[];

__device__ __forceinline__ uint32_t smem_u32(const void* p) {
    uint32_t a;
    asm("{ .reg .u64 t; cvta.to.shared.u64 t, %1; cvt.u32.u64 %0, t; }"
        : "=r"(a) : "l"(p));
    return a;
}
__device__ __forceinline__ void cluster_sync_() {
    asm volatile("barrier.cluster.arrive.aligned;" ::: "memory");
    asm volatile("barrier.cluster.wait.aligned;" ::: "memory");
}
__device__ __forceinline__ void red_remote_add_f32(uint32_t laddr, uint32_t rank, float v) {
    asm volatile(
        "{ .reg .b32 r; mapa.shared::cluster.u32 r, %0, %1; "
        "red.relaxed.cluster.shared::cluster.add.f32 [r], %2; }"
        :: "r"(laddr), "r"(rank), "f"(v) : "memory");
}
__device__ __forceinline__ float ex2f_(float x) {
    float y; asm("ex2.approx.ftz.f32 %0, %1;" : "=f"(y) : "f"(x)); return y;
}
__device__ __forceinline__ float lg2f_(float x) {
    float y; asm("lg2.approx.ftz.f32 %0, %1;" : "=f"(y) : "f"(x)); return y;
}
__device__ __forceinline__ float rcpf_(float x) {
    float y; asm("rcp.approx.ftz.f32 %0, %1;" : "=f"(y) : "f"(x)); return y;
}
__device__ __forceinline__ bool mask_at(const void* m, bool byteMask, int idx) {
    if (byteMask) return ((const unsigned char*)m)[idx] != 0;
    return ((const uint32_t*)m)[idx] != 0u;
}

__global__ void __launch_bounds__(NTH, 3) __cluster_dims__(6, 1, 1)
lbp_kernel(const float* __restrict__ s_edge,
           const float* __restrict__ s_sib,
           const float* __restrict__ s_cop,
           const float* __restrict__ s_grd,
           const void* __restrict__ mask,
           float* __restrict__ out)
{
    const int tid  = threadIdx.x;
    const int bx   = blockIdx.x;
    const int rank = bx % 6;
    const int prob = bx / 6;
    const int i    = prob % S;
    const int b    = prob / S;
    const int t    = rank >> 1;      /* score type */
    const int c    = rank & 1;       /* pair-parity class */

    const int tr    = tid & 31;              /* lane: row group */
    const int tc    = tid >> 5;              /* warp: col group */
    const int par   = c ^ (tr & 1);          /* fixed column parity */
    const int kbase = 10 * tc + par;         /* k_s = kbase + 2s */

    const bool byteMask = (*(const uint32_t*)mask == 0x01010101u);

    float* __restrict__ X  = sm + OFF_X;
    float* __restrict__ DB = sm + OFF_DB;
    float* __restrict__ EX = sm + OFF_EX;

    const float* __restrict__ Praw =
        (t == 0 ? s_sib : (t == 1 ? s_cop : s_grd)) + (size_t)b * S3 + i * S;
    float* __restrict__ P2 = P2g + ((size_t)(b * S + i) * 6 + rank) * 12800;

    /* per-thread bases: raw p at [k][j], scratch at [k][jh] */
    const float* __restrict__ pb  = Praw + (size_t)kbase * S2 + tr;
    float*       __restrict__ p2b = P2 + kbase * 80 + (tr >> 1);

    /* ---- init scalars (X needs no init: it=0 writes every cell) ---- */
    if (tid < S) {
        const int k = tid;
        const bool mk = mask_at(mask, byteMask, b * S2 + k * S + i);
        sm[OFF_W  + k] = (mk && (k != i)) ? 1.f : 0.f;
        sm[OFF_MJ + k] = mk ? 1.f : 0.f;
        sm[OFF_SE + k] = s_edge[b * S2 + k * S + i] * LOG2E;
        DB[k] = 0.f;
        EX[k] = 1.f;
        sm[OFF_RS + k] = 0.f;
        sm[OFF_ACC + k] = 0.f;
        sm[OFF_ACC + S + k] = 0.f;
    }
    __syncthreads();
    cluster_sync_();   /* all ranks' ACC zeroed before any remote red */

    const uint32_t accAddr = smem_u32(sm + OFF_ACC);
    float dbFinal = 0.f;

    /* hoisted per-column weights (constant across iterations) */
    float Wreg[5];
    #pragma unroll
    for (int s = 0; s < 5; ++s) Wreg[s] = sm[OFF_W + kbase + 2 * s];

    for (int it = 0; it < 3; ++it) {
        float acc[5];

        if (it == 0) {
            /* Xold = 1, E = 1 -> e = 1. Compute Pv from raw p; persist it. */
            #pragma unroll
            for (int r = 0; r < 5; ++r) {
                const int jv = tr + 32 * r;
                const int wrow = jv * DP + 5 * tc;
                float av = 0.f;
                #pragma unroll
                for (int s = 0; s < 5; ++s) {
                    const int k = kbase + 2 * s;
                    const float Pv = ex2f_(pb[(size_t)2 * s * S2 + 32 * r] * LOG2E);
                    p2b[160 * s + 16 * r] = Pv;
                    const float rr = 2.f * rcpf_(1.f + Pv);   /* 2^(-d_new) */
                    X[wrow + s] = rr;
                    const float dn = lg2f_(rr);               /* = -d_new */
                    const float wc = (k == jv) ? 0.f : Wreg[s];
                    av = fmaf(wc, dn, av);
                }
                acc[r] = av;
            }
        } else {
            /* stage transpose partners X_old[k][jv] into regs */
            float Xold[25];
            #pragma unroll
            for (int r = 0; r < 5; ++r) {
                const int rb = (tr >> 1) + 16 * r;
                #pragma unroll
                for (int s = 0; s < 5; ++s)
                    Xold[r * 5 + s] = X[(kbase + 2 * s) * DP + rb];
            }
            __syncthreads();   /* all reads before any writes */

            float Ereg[5];
            #pragma unroll
            for (int s = 0; s < 5; ++s) Ereg[s] = EX[kbase + 2 * s];

            #pragma unroll
            for (int r = 0; r < 5; ++r) {
                const int jv = tr + 32 * r;
                const int wrow = jv * DP + 5 * tc;
                float av = 0.f;
                #pragma unroll
                for (int s = 0; s < 5; ++s) {
                    const int k  = kbase + 2 * s;
                    const float Pv = p2b[160 * s + 16 * r];   /* L2-hot */
                    const float e  = Ereg[s] * Xold[r * 5 + s];
                    const float num = fmaf(e, Pv, 1.f);
                    const float den = e + 1.f;
                    const float rr  = den * rcpf_(num);       /* 2^(-d_new) */
                    X[wrow + s] = rr;
                    const float dn  = lg2f_(rr);              /* = -d_new */
                    const float wc  = (k == jv) ? 0.f : Wreg[s];
                    av = fmaf(wc, dn, av);
                }
                acc[r] = av;
            }
        }

        #pragma unroll
        for (int r = 0; r < 5; ++r)
            atomicAdd(&sm[OFF_RS + tr + 32 * r], acc[r]);
        __syncthreads();   /* X writes + RS complete */

        /* ---- Δb all-reduce across the 6 ranks (RS holds -rowsum) ---- */
        const int buf = it & 1;
        float myPart = 0.f;
        if (tid < S) {
            myPart = sm[OFF_RS + tid];
            const uint32_t dst = accAddr + 4u * (uint32_t)(buf * S + tid);
            #pragma unroll
            for (int r = 0; r < 6; ++r)
                if (r != rank) red_remote_add_f32(dst, (uint32_t)r, myPart);
        }
        cluster_sync_();   /* peer partials landed */
        if (tid < S) {
            const float tot = -(myPart + sm[OFF_ACC + buf * S + tid]);
            sm[OFF_ACC + buf * S + tid] = 0.f;      /* re-arm for it+2 */
            sm[OFF_RS + tid] = 0.f;
            dbFinal = sm[OFF_SE + tid] + sm[OFF_MJ + tid] * tot;
            DB[tid] = dbFinal;
            EX[tid] = ex2f_(fminf(fmaxf(dbFinal, -30.f), 30.f));
        }
        /* next iter's stage __syncthreads orders DB/EX/RS/ACC */
    }

    /* ---- output: out[b, j, i, :] = softmax over channels (base-2) ---- */
    if (rank == 0 && tid < S) {
        const float Dv = dbFinal;
        const float e  = ex2f_(-fabsf(Dv));
        const float pb_ = 1.f / (1.f + e);
        const float ps = e * pb_;
        const float p1 = (Dv >= 0.f) ? pb_ : ps;
        const float p0 = (Dv >= 0.f) ? ps : pb_;
        float* o = out + ((size_t)((b * S + tid) * S + i)) * 2;
        o[0] = p0;
        o[1] = p1;
    }
}

extern "C" void kernel_launch(void* const* d_in, const int* in_sizes, int n_in,
                              void* d_out, int out_size) {
    (void)in_sizes; (void)n_in; (void)out_size;
    cudaFuncSetAttribute(lbp_kernel,
                         cudaFuncAttributeMaxDynamicSharedMemorySize, SMEM_BYTES);
    const float* s_edge = (const float*)d_in[0];
    const float* s_sib  = (const float*)d_in[1];
    const float* s_cop  = (const float*)d_in[2];
    const float* s_grd  = (const float*)d_in[3];
    const void*  mask   = d_in[4];
    float* outp = (float*)d_out;

    lbp_kernel<<<2 * S * 6, NTH, SMEM_BYTES>>>(
        s_edge, s_sib, s_cop, s_grd, mask, outp);
}